// round 6
// baseline (speedup 1.0000x reference)
#include <cuda_runtime.h>

#define HC 16
#define PQ (2048 * 2048)   /* 4,194,304 rows  */
#define PF (2048 * 4096)   /* 8,388,608 rows  */

// h_q in [0..15], h_ffn in [16..31]
__device__ float g_h[32];

// ---------------------------------------------------------------------------
// Warp-parallel prologue (1 warp): hypercube gather -> 16-pt rfft -> complex
// filter -> irfft -> Haar, for BOTH heads. Stage-parallel with __syncwarp
// between stages; twiddles from a 16-entry cos/sin(m*pi/8) table using
// (k*n) mod 16 periodicity.
// irfft semantics (pocketfft C2R): imag parts of DC and Nyquist ignored.
// ---------------------------------------------------------------------------
__global__ void prologue_kernel(const float* __restrict__ ctx,
                                const float* __restrict__ hyper,
                                const float* __restrict__ fw_q,
                                const float* __restrict__ ps_q,
                                const float* __restrict__ fw_f,
                                const float* __restrict__ ps_f) {
    __shared__ float tc[16], tsn[16];
    __shared__ float Sr[9], Si[9];
    __shared__ float Rr[2][9], Ri[2][9];
    __shared__ float f[2][16];

    const int tid = threadIdx.x;
    const float PI = 3.14159265358979323846f;

    // Stage A: twiddle table cos/sin(m*pi/8)
    if (tid < 16) {
        float sn, cs;
        sincosf((float)tid * (PI / 8.0f), &sn, &cs);
        tc[tid] = cs; tsn[tid] = sn;
    }
    __syncwarp();

    // Stage B: rfft bins k = 0..8 (shared by both heads)
    if (tid < 9) {
        int i0 = (int)(ctx[0] * 15.0f);
        int i1 = (int)(ctx[1] * 15.0f);
        int i2 = (int)(ctx[2] * 15.0f);
        const float* s = hyper + (((size_t)i0 * HC + i1) * HC + i2) * HC;
        float re = 0.0f, im = 0.0f;
#pragma unroll
        for (int n = 0; n < 16; n++) {
            int m = (tid * n) & 15;
            float sv = s[n];
            re += sv * tc[m];
            im -= sv * tsn[m];
        }
        Sr[tid] = re; Si[tid] = im;
    }
    __syncwarp();

    // Stage C: complex filter, both heads (18 lanes)
    if (tid < 18) {
        int head = tid / 9, k = tid % 9;
        float a  = head ? fw_f[k] : fw_q[k];
        float bb = head ? ps_f[k] : ps_q[k];
        Rr[head][k] = Sr[k] * a - Si[k] * bb;
        Ri[head][k] = Sr[k] * bb + Si[k] * a;
    }
    __syncwarp();

    // Stage D: irfft, 16 n x 2 heads (32 lanes)
    {
        int head = tid >> 4, n = tid & 15;
        float acc = Rr[head][0] + ((n & 1) ? -Rr[head][8] : Rr[head][8]);
#pragma unroll
        for (int k = 1; k <= 7; k++) {
            int m = (k * n) & 15;
            acc += 2.0f * (Rr[head][k] * tc[m] - Ri[head][k] * tsn[m]);
        }
        f[head][n] = acc * (1.0f / 16.0f);
    }
    __syncwarp();

    // Stage E: Haar, 8 j x 2 heads (16 lanes)
    if (tid < 16) {
        const float inv_sqrt2 = 0.7071067811865476f;
        int head = tid >> 3, j = tid & 7;
        g_h[head * 16 + j]     = (f[head][2 * j] + f[head][2 * j + 1]) * inv_sqrt2;
        g_h[head * 16 + 8 + j] = (f[head][2 * j] - f[head][2 * j + 1]) * inv_sqrt2;
    }
}

// ---------------------------------------------------------------------------
// Main GEMV, fully coalesced (R2 body, byte-for-byte: 32 regs, occ 94%).
// Unit = one float4 of W (quarter-row). Thread tid owns quarter (tid&3).
// 8 coalesced LDG.128 front-batched (MLP=8); 4-FFMA partial dots +
// shfl.bfly(1,2) reduction; lane q==0 adds bias and stores.
// ---------------------------------------------------------------------------
#define UNROLL 8
#define TPB 256
#define UNITS_PER_BLOCK (UNROLL * TPB)          /* 2048 float4 units */
#define QB ((PQ * 4) / UNITS_PER_BLOCK)         /* 8192 blocks  */
#define FB ((PF * 4) / UNITS_PER_BLOCK)         /* 16384 blocks */

__global__ void __launch_bounds__(TPB)
gemv_kernel(const float4* __restrict__ Wq, const float* __restrict__ bq,
            const float4* __restrict__ Wf, const float* __restrict__ bf,
            float* __restrict__ out) {
    const int tid = threadIdx.x;
    const bool isQ = (blockIdx.x < QB);

    const float4* __restrict__ W;
    const float*  __restrict__ b;
    float* __restrict__ o;
    size_t ubase;  // first float4 unit of this block
    if (isQ) {
        W = Wq; b = bq; o = out;
        ubase = (size_t)blockIdx.x * UNITS_PER_BLOCK;
    } else {
        W = Wf; b = bf; o = out + PQ;
        ubase = (size_t)(blockIdx.x - QB) * UNITS_PER_BLOCK;
    }

    // Front-batched, fully coalesced loads (MLP = 8)
    float4 w[UNROLL];
#pragma unroll
    for (int j = 0; j < UNROLL; j++)
        w[j] = W[ubase + (size_t)j * TPB + tid];

    const int q = tid & 3;   // which quarter of h this thread handles
    float h0, h1, h2, h3;
    {
        const float* hh = g_h + (isQ ? 0 : 16) + 4 * q;
        h0 = hh[0]; h1 = hh[1]; h2 = hh[2]; h3 = hh[3];
    }

#pragma unroll
    for (int j = 0; j < UNROLL; j++) {
        float p = w[j].x * h0 + w[j].y * h1 + w[j].z * h2 + w[j].w * h3;
        p += __shfl_xor_sync(0xffffffffu, p, 1);
        p += __shfl_xor_sync(0xffffffffu, p, 2);
        if (q == 0) {
            size_t row = (ubase + (size_t)j * TPB + tid) >> 2;
            o[row] = p + b[row];
        }
    }
}

// ---------------------------------------------------------------------------
// Launch: plain serialized launches (PDL measured counterproductive: its
// +2 regs drop gemv occupancy 94% -> 70%).
// Inputs (metadata order): context(3), hypercube(65536), fw_q(9), ps_q(9),
// W_q(PQ*16), b_q(PQ), fw_ffn(9), ps_ffn(9), W_ffn(PF*16), b_ffn(PF)
// ---------------------------------------------------------------------------
extern "C" void kernel_launch(void* const* d_in, const int* in_sizes, int n_in,
                              void* d_out, int out_size) {
    const float* ctx    = (const float*)d_in[0];
    const float* hyper  = (const float*)d_in[1];
    const float* fw_q   = (const float*)d_in[2];
    const float* ps_q   = (const float*)d_in[3];
    const float* W_q    = (const float*)d_in[4];
    const float* b_q    = (const float*)d_in[5];
    const float* fw_ffn = (const float*)d_in[6];
    const float* ps_ffn = (const float*)d_in[7];
    const float* W_ffn  = (const float*)d_in[8];
    const float* b_ffn  = (const float*)d_in[9];

    prologue_kernel<<<1, 32>>>(ctx, hyper, fw_q, ps_q, fw_ffn, ps_ffn);

    gemv_kernel<<<QB + FB, TPB>>>(
        (const float4*)W_q, b_q,
        (const float4*)W_ffn, b_ffn,
        (float*)d_out);
}

// round 7
// speedup vs baseline: 1.0194x; 1.0194x over previous
#include <cuda_runtime.h>

#define HC 16
#define PQ (2048 * 2048)   /* 4,194,304 rows  */
#define PF (2048 * 4096)   /* 8,388,608 rows  */

// h_q in [0..15], h_ffn in [16..31]
__device__ float g_h[32];

// ---------------------------------------------------------------------------
// Warp-parallel prologue (1 warp): hypercube gather -> 16-pt rfft -> complex
// filter -> irfft -> Haar, for BOTH heads. Stage-parallel with __syncwarp
// between stages; twiddles from a 16-entry cos/sin(m*pi/8) table using
// (k*n) mod 16 periodicity.
// irfft semantics (pocketfft C2R): imag parts of DC and Nyquist ignored.
// ---------------------------------------------------------------------------
__global__ void prologue_kernel(const float* __restrict__ ctx,
                                const float* __restrict__ hyper,
                                const float* __restrict__ fw_q,
                                const float* __restrict__ ps_q,
                                const float* __restrict__ fw_f,
                                const float* __restrict__ ps_f) {
    __shared__ float tc[16], tsn[16];
    __shared__ float Sr[9], Si[9];
    __shared__ float Rr[2][9], Ri[2][9];
    __shared__ float f[2][16];

    const int tid = threadIdx.x;
    const float PI = 3.14159265358979323846f;

    // Stage A: twiddle table cos/sin(m*pi/8)
    if (tid < 16) {
        float sn, cs;
        sincosf((float)tid * (PI / 8.0f), &sn, &cs);
        tc[tid] = cs; tsn[tid] = sn;
    }
    __syncwarp();

    // Stage B: rfft bins k = 0..8 (shared by both heads)
    if (tid < 9) {
        int i0 = (int)(ctx[0] * 15.0f);
        int i1 = (int)(ctx[1] * 15.0f);
        int i2 = (int)(ctx[2] * 15.0f);
        const float* s = hyper + (((size_t)i0 * HC + i1) * HC + i2) * HC;
        float re = 0.0f, im = 0.0f;
#pragma unroll
        for (int n = 0; n < 16; n++) {
            int m = (tid * n) & 15;
            float sv = s[n];
            re += sv * tc[m];
            im -= sv * tsn[m];
        }
        Sr[tid] = re; Si[tid] = im;
    }
    __syncwarp();

    // Stage C: complex filter, both heads (18 lanes)
    if (tid < 18) {
        int head = tid / 9, k = tid % 9;
        float a  = head ? fw_f[k] : fw_q[k];
        float bb = head ? ps_f[k] : ps_q[k];
        Rr[head][k] = Sr[k] * a - Si[k] * bb;
        Ri[head][k] = Sr[k] * bb + Si[k] * a;
    }
    __syncwarp();

    // Stage D: irfft, 16 n x 2 heads (32 lanes)
    {
        int head = tid >> 4, n = tid & 15;
        float acc = Rr[head][0] + ((n & 1) ? -Rr[head][8] : Rr[head][8]);
#pragma unroll
        for (int k = 1; k <= 7; k++) {
            int m = (k * n) & 15;
            acc += 2.0f * (Rr[head][k] * tc[m] - Ri[head][k] * tsn[m]);
        }
        f[head][n] = acc * (1.0f / 16.0f);
    }
    __syncwarp();

    // Stage E: Haar, 8 j x 2 heads (16 lanes)
    if (tid < 16) {
        const float inv_sqrt2 = 0.7071067811865476f;
        int head = tid >> 3, j = tid & 7;
        g_h[head * 16 + j]     = (f[head][2 * j] + f[head][2 * j + 1]) * inv_sqrt2;
        g_h[head * 16 + 8 + j] = (f[head][2 * j] - f[head][2 * j + 1]) * inv_sqrt2;
    }
}

// ---------------------------------------------------------------------------
// Main GEMV, fully coalesced. __launch_bounds__(TPB, 8) FORCES the 32-reg /
// 8-blocks-per-SM allocation that R2 measured at 87.4% DRAM; since R4 ptxas
// has been drifting to 34 regs -> 6 blocks/SM -> 84% DRAM.
// Unit = one float4 of W (quarter-row). Thread tid owns quarter (tid&3).
// 8 coalesced LDG.128 front-batched (MLP=8); 4-FFMA partial dots +
// shfl.bfly(1,2) reduction; lane q==0 adds bias and stores.
// ---------------------------------------------------------------------------
#define UNROLL 8
#define TPB 256
#define UNITS_PER_BLOCK (UNROLL * TPB)          /* 2048 float4 units */
#define QB ((PQ * 4) / UNITS_PER_BLOCK)         /* 8192 blocks  */
#define FB ((PF * 4) / UNITS_PER_BLOCK)         /* 16384 blocks */

__global__ void __launch_bounds__(TPB, 8)
gemv_kernel(const float4* __restrict__ Wq, const float* __restrict__ bq,
            const float4* __restrict__ Wf, const float* __restrict__ bf,
            float* __restrict__ out) {
    const int tid = threadIdx.x;
    const bool isQ = (blockIdx.x < QB);

    const float4* __restrict__ W;
    const float*  __restrict__ b;
    float* __restrict__ o;
    size_t ubase;  // first float4 unit of this block
    if (isQ) {
        W = Wq; b = bq; o = out;
        ubase = (size_t)blockIdx.x * UNITS_PER_BLOCK;
    } else {
        W = Wf; b = bf; o = out + PQ;
        ubase = (size_t)(blockIdx.x - QB) * UNITS_PER_BLOCK;
    }

    // Front-batched, fully coalesced loads (MLP = 8)
    float4 w[UNROLL];
#pragma unroll
    for (int j = 0; j < UNROLL; j++)
        w[j] = W[ubase + (size_t)j * TPB + tid];

    const int q = tid & 3;   // which quarter of h this thread handles
    float h0, h1, h2, h3;
    {
        const float* hh = g_h + (isQ ? 0 : 16) + 4 * q;
        h0 = hh[0]; h1 = hh[1]; h2 = hh[2]; h3 = hh[3];
    }

#pragma unroll
    for (int j = 0; j < UNROLL; j++) {
        float p = w[j].x * h0 + w[j].y * h1 + w[j].z * h2 + w[j].w * h3;
        p += __shfl_xor_sync(0xffffffffu, p, 1);
        p += __shfl_xor_sync(0xffffffffu, p, 2);
        if (q == 0) {
            size_t row = (ubase + (size_t)j * TPB + tid) >> 2;
            o[row] = p + b[row];
        }
    }
}

// ---------------------------------------------------------------------------
// Launch: plain serialized launches (PDL measured counterproductive).
// Inputs (metadata order): context(3), hypercube(65536), fw_q(9), ps_q(9),
// W_q(PQ*16), b_q(PQ), fw_ffn(9), ps_ffn(9), W_ffn(PF*16), b_ffn(PF)
// ---------------------------------------------------------------------------
extern "C" void kernel_launch(void* const* d_in, const int* in_sizes, int n_in,
                              void* d_out, int out_size) {
    const float* ctx    = (const float*)d_in[0];
    const float* hyper  = (const float*)d_in[1];
    const float* fw_q   = (const float*)d_in[2];
    const float* ps_q   = (const float*)d_in[3];
    const float* W_q    = (const float*)d_in[4];
    const float* b_q    = (const float*)d_in[5];
    const float* fw_ffn = (const float*)d_in[6];
    const float* ps_ffn = (const float*)d_in[7];
    const float* W_ffn  = (const float*)d_in[8];
    const float* b_ffn  = (const float*)d_in[9];

    prologue_kernel<<<1, 32>>>(ctx, hyper, fw_q, ps_q, fw_ffn, ps_ffn);

    gemv_kernel<<<QB + FB, TPB>>>(
        (const float4*)W_q, b_q,
        (const float4*)W_ffn, b_ffn,
        (float*)d_out);
}